// round 1
// baseline (speedup 1.0000x reference)
#include <cuda_runtime.h>

#define DIM 128
#define N 512
#define HEADS 4
#define DH 32
#define HID 128
#define IND 5
#define ATTN_SCALE 0.17677669529663687f   // 32^-0.5

// Scratch (allocation-free rule: __device__ globals)
__device__ float g_qkv[3 * HID * N];        // [384][512]  rows: q(0..127) k(128..255) v(256..383)
__device__ float g_A2[HEADS * IND * N];     // [h][c][i]
__device__ float g_B3[HEADS * IND * N];     // [h][c][j]
__device__ float g_W4[HEADS * IND * IND];   // [h][c][c']
__device__ float g_av[HID * N];             // attn @ v, [h*32+d][i]

// ---------------------------------------------------------------------------
// K1: qkv = w_qkv (384x128) @ x (128x512).  One block per 4 columns.
// ---------------------------------------------------------------------------
__global__ void k_qkv(const float* __restrict__ x, const float* __restrict__ w_qkv) {
    __shared__ float xs[4 * DIM];
    const int i0 = blockIdx.x * 4;
    const int t = threadIdx.x;            // 384 threads, one output row each

    for (int idx = t; idx < 4 * DIM; idx += blockDim.x) {
        int c = idx >> 2, col = idx & 3;
        xs[col * DIM + c] = x[c * N + i0 + col];
    }
    __syncthreads();

    const float* w = w_qkv + t * DIM;
    float a0 = 0.f, a1 = 0.f, a2 = 0.f, a3 = 0.f;
#pragma unroll 8
    for (int c = 0; c < DIM; c++) {
        float wv = w[c];
        a0 = fmaf(wv, xs[c],           a0);
        a1 = fmaf(wv, xs[DIM + c],     a1);
        a2 = fmaf(wv, xs[2 * DIM + c], a2);
        a3 = fmaf(wv, xs[3 * DIM + c], a3);
    }
    g_qkv[t * N + i0 + 0] = a0;
    g_qkv[t * N + i0 + 1] = a1;
    g_qkv[t * N + i0 + 2] = a2;
    g_qkv[t * N + i0 + 3] = a3;
}

// ---------------------------------------------------------------------------
// K2: A2[h,c,i], B3[h,c,i] (per-column 32-dots) and W4 (block 0 only).
// grid = 512 (i), block = 160 threads.
// ---------------------------------------------------------------------------
__global__ void k_small(const float* __restrict__ w_ind) {
    const int i = blockIdx.x;
    const int t = threadIdx.x;
    if (t < 20) {                 // A2: q . wk_ind
        int h = t / 5, c = t % 5;
        float acc = 0.f;
#pragma unroll
        for (int d = 0; d < DH; d++)
            acc = fmaf(g_qkv[(h * DH + d) * N + i],
                       w_ind[(HID + h * DH + d) * IND + c], acc);
        g_A2[(h * IND + c) * N + i] = acc;
    } else if (t < 40) {          // B3: k . wq_ind
        int u = t - 20, h = u / 5, c = u % 5;
        float acc = 0.f;
#pragma unroll
        for (int d = 0; d < DH; d++)
            acc = fmaf(g_qkv[(HID + h * DH + d) * N + i],
                       w_ind[(h * DH + d) * IND + c], acc);
        g_B3[(h * IND + c) * N + i] = acc;
    } else if (blockIdx.x == 0 && t < 140) {   // W4: wq_ind^T wk_ind per head
        int u = t - 40;
        int h = u / 25, c = (u % 25) / 5, cp = u % 5;
        float acc = 0.f;
#pragma unroll
        for (int d = 0; d < DH; d++)
            acc = fmaf(w_ind[(h * DH + d) * IND + c],
                       w_ind[(HID + h * DH + d) * IND + cp], acc);
        g_W4[u] = acc;
    }
}

// ---------------------------------------------------------------------------
// K3: fused sim -> softmax -> attn@v.  One block per (i, h), 512 threads (j).
// ---------------------------------------------------------------------------
__global__ __launch_bounds__(512) void k_attn(const float* __restrict__ indicator) {
    const int i = blockIdx.x;
    const int h = blockIdx.y;
    const int j = threadIdx.x;
    const int warp = j >> 5, lane = j & 31;

    __shared__ float qs[DH];
    __shared__ float a2s[IND];
    __shared__ float w4s[IND * IND];
    __shared__ float attn[N];
    __shared__ float red[16];

    if (j < DH)                      qs[j] = g_qkv[(h * DH + j) * N + i];
    else if (j < DH + IND)           a2s[j - DH] = g_A2[(h * IND + (j - DH)) * N + i];
    else if (j < DH + IND + 25)      w4s[j - DH - IND] = g_W4[h * 25 + (j - DH - IND)];
    __syncthreads();

    // --- sim[j] ---
    const float* kbase = g_qkv + (HID + h * DH) * N;
    float qk = 0.f;
#pragma unroll
    for (int d = 0; d < DH; d++)
        qk = fmaf(qs[d], kbase[d * N + j], qk);

    float iv[IND];
#pragma unroll
    for (int c = 0; c < IND; c++)
        iv[c] = indicator[(size_t)c * N * N + (size_t)i * N + j];

    float lin = 0.f;
#pragma unroll
    for (int c = 0; c < IND; c++)
        lin = fmaf(iv[c], a2s[c] + g_B3[(h * IND + c) * N + j], lin);

    float quad = 0.f;
#pragma unroll
    for (int c = 0; c < IND; c++) {
        float t2 = 0.f;
#pragma unroll
        for (int cp = 0; cp < IND; cp++)
            t2 = fmaf(w4s[c * IND + cp], iv[cp], t2);
        quad = fmaf(iv[c], t2, quad);
    }

    float sim = ATTN_SCALE * (qk + lin + quad);

    // --- softmax (unnormalized; scale at the end) ---
    float m = sim;
#pragma unroll
    for (int off = 16; off; off >>= 1)
        m = fmaxf(m, __shfl_xor_sync(0xffffffffu, m, off));
    if (lane == 0) red[warp] = m;
    __syncthreads();
    float gmax = red[0];
#pragma unroll
    for (int w = 1; w < 16; w++) gmax = fmaxf(gmax, red[w]);

    float e = __expf(sim - gmax);
    attn[j] = e;
    float s = e;
#pragma unroll
    for (int off = 16; off; off >>= 1)
        s += __shfl_xor_sync(0xffffffffu, s, off);
    __syncthreads();                 // red reads done, attn writes landed
    if (lane == 0) red[warp] = s;
    __syncthreads();
    float gsum = 0.f;
#pragma unroll
    for (int w = 0; w < 16; w++) gsum += red[w];
    const float inv = 1.0f / gsum;

    // --- out[h,d,i] = inv * sum_j attn[j] * v[h,d,j] ---
    const float* vbase = g_qkv + (2 * HID + h * DH) * N;
#pragma unroll
    for (int d = warp; d < DH; d += 16) {
        const float* vrow = vbase + d * N;
        float acc = 0.f;
#pragma unroll
        for (int jj = lane; jj < N; jj += 32)
            acc = fmaf(attn[jj], vrow[jj], acc);
#pragma unroll
        for (int off = 16; off; off >>= 1)
            acc += __shfl_xor_sync(0xffffffffu, acc, off);
        if (lane == 0) g_av[(h * DH + d) * N + i] = acc * inv;
    }
}

// ---------------------------------------------------------------------------
// K4: out = w_out (128x128) @ g_av (128x512) + b_out
// ---------------------------------------------------------------------------
__global__ void k_proj(const float* __restrict__ w_out,
                       const float* __restrict__ b_out,
                       float* __restrict__ out) {
    __shared__ float cs[HID];
    const int i = blockIdx.x;
    const int o = threadIdx.x;       // 128 threads
    cs[o] = g_av[o * N + i];
    __syncthreads();
    float acc = b_out[o];
    const float* w = w_out + o * HID;
#pragma unroll 8
    for (int c = 0; c < HID; c++)
        acc = fmaf(w[c], cs[c], acc);
    out[o * N + i] = acc;
}

// ---------------------------------------------------------------------------
extern "C" void kernel_launch(void* const* d_in, const int* in_sizes, int n_in,
                              void* d_out, int out_size) {
    const float* x         = (const float*)d_in[0];   // (1,128,512)
    const float* indicator = (const float*)d_in[1];   // (1,5,512,512)
    const float* w_qkv     = (const float*)d_in[2];   // (384,128)
    const float* w_ind     = (const float*)d_in[3];   // (256,5)
    const float* w_out     = (const float*)d_in[4];   // (128,128)
    const float* b_out     = (const float*)d_in[5];   // (128,)
    float* out             = (float*)d_out;           // (1,128,512)

    k_qkv<<<N / 4, 384>>>(x, w_qkv);
    k_small<<<N, 160>>>(w_ind);
    {
        dim3 grid(N, HEADS);
        k_attn<<<grid, N>>>(indicator);
    }
    k_proj<<<N, HID>>>(w_out, b_out, out);
}

// round 3
// speedup vs baseline: 2.2012x; 2.2012x over previous
#include <cuda_runtime.h>

#define DIM 128
#define N 512
#define HEADS 4
#define DH 32
#define HID 128
#define IND 5
#define ATTN_SCALE 0.17677669529663687f   // 32^-0.5

// Scratch (allocation-free rule: __device__ globals). 256B-aligned: these are
// accessed with float4 loads/stores.
__device__ __align__(256) float g_qkv[3 * HID * N];   // [384][512] q|k|v
__device__ __align__(256) float g_A2[HEADS * IND * N];
__device__ __align__(256) float g_B3[HEADS * IND * N];
__device__ __align__(256) float g_W4[HEADS * IND * IND];
__device__ __align__(256) float g_qk[HEADS * N * N];  // [h][i][j]
__device__ __align__(256) float g_av[HID * N];        // [h*32+d][i]

// ---------------------------------------------------------------------------
// Tiled GEMM: C[M][Nn] = A[M][K] @ B[K][Nn] (+bias).  TM=32, TN=64, TK=16,
// 256 threads, 2x4 register tile. grid = (Nn/64, M/32).
// ---------------------------------------------------------------------------
template<int M, int K, int Nn, bool BIAS>
__global__ __launch_bounds__(256) void k_gemm(const float* __restrict__ A,
                                              const float* __restrict__ B,
                                              const float* __restrict__ bias,
                                              float* __restrict__ C) {
    __shared__ float As[16][32];
    __shared__ float Bs[16][64];
    const int n0 = blockIdx.x * 64;
    const int m0 = blockIdx.y * 32;
    const int t  = threadIdx.x;
    const int tx = t & 15;          // n sub-tile (x4)
    const int ty = t >> 4;          // m sub-tile (x2)

    float acc[2][4] = {};
    for (int k0 = 0; k0 < K; k0 += 16) {
#pragma unroll
        for (int idx = t; idx < 512; idx += 256) {       // As 16x32
            int kk = idx & 15, m = idx >> 4;
            As[kk][m] = A[(m0 + m) * K + k0 + kk];
        }
#pragma unroll
        for (int idx = t; idx < 1024; idx += 256) {      // Bs 16x64
            int n = idx & 63, kk = idx >> 6;
            Bs[kk][n] = B[(k0 + kk) * Nn + n0 + n];
        }
        __syncthreads();
#pragma unroll
        for (int kk = 0; kk < 16; kk++) {
            float2 a = ((const float2*)&As[kk][0])[ty];
            float4 b = ((const float4*)&Bs[kk][0])[tx];
            acc[0][0] = fmaf(a.x, b.x, acc[0][0]);
            acc[0][1] = fmaf(a.x, b.y, acc[0][1]);
            acc[0][2] = fmaf(a.x, b.z, acc[0][2]);
            acc[0][3] = fmaf(a.x, b.w, acc[0][3]);
            acc[1][0] = fmaf(a.y, b.x, acc[1][0]);
            acc[1][1] = fmaf(a.y, b.y, acc[1][1]);
            acc[1][2] = fmaf(a.y, b.z, acc[1][2]);
            acc[1][3] = fmaf(a.y, b.w, acc[1][3]);
        }
        __syncthreads();
    }
#pragma unroll
    for (int r = 0; r < 2; r++) {
        int m = m0 + ty * 2 + r;
        float o0 = acc[r][0], o1 = acc[r][1], o2 = acc[r][2], o3 = acc[r][3];
        if (BIAS) { float bv = bias[m]; o0 += bv; o1 += bv; o2 += bv; o3 += bv; }
        float* cp = &C[m * Nn + n0 + tx * 4];
        cp[0] = o0; cp[1] = o1; cp[2] = o2; cp[3] = o3;   // scalar stores: C alignment unknown
    }
}

// ---------------------------------------------------------------------------
// k_qk: g_qk[h][i][j] = sum_d q[h,d,i]*k[h,d,j].  64x64 tile, 4x4 rtile.
// grid (8, 8, 4), 256 threads.
// ---------------------------------------------------------------------------
__global__ __launch_bounds__(256) void k_qk() {
    __shared__ float qs[DH][64];
    __shared__ float ks[DH][64];
    const int j0 = blockIdx.x * 64;
    const int i0 = blockIdx.y * 64;
    const int h  = blockIdx.z;
    const int t  = threadIdx.x;
    const int tx = t & 15, ty = t >> 4;

    const float* qb = g_qkv + (h * DH) * N;
    const float* kb = g_qkv + (HID + h * DH) * N;
#pragma unroll
    for (int idx = t; idx < DH * 64; idx += 256) {
        int d = idx >> 6, c = idx & 63;
        qs[d][c] = qb[d * N + i0 + c];
        ks[d][c] = kb[d * N + j0 + c];
    }
    __syncthreads();

    float acc[4][4] = {};
#pragma unroll
    for (int d = 0; d < DH; d++) {
        float4 qa = ((const float4*)&qs[d][0])[ty];
        float4 kv = ((const float4*)&ks[d][0])[tx];
        acc[0][0] = fmaf(qa.x, kv.x, acc[0][0]);
        acc[0][1] = fmaf(qa.x, kv.y, acc[0][1]);
        acc[0][2] = fmaf(qa.x, kv.z, acc[0][2]);
        acc[0][3] = fmaf(qa.x, kv.w, acc[0][3]);
        acc[1][0] = fmaf(qa.y, kv.x, acc[1][0]);
        acc[1][1] = fmaf(qa.y, kv.y, acc[1][1]);
        acc[1][2] = fmaf(qa.y, kv.z, acc[1][2]);
        acc[1][3] = fmaf(qa.y, kv.w, acc[1][3]);
        acc[2][0] = fmaf(qa.z, kv.x, acc[2][0]);
        acc[2][1] = fmaf(qa.z, kv.y, acc[2][1]);
        acc[2][2] = fmaf(qa.z, kv.z, acc[2][2]);
        acc[2][3] = fmaf(qa.z, kv.w, acc[2][3]);
        acc[3][0] = fmaf(qa.w, kv.x, acc[3][0]);
        acc[3][1] = fmaf(qa.w, kv.y, acc[3][1]);
        acc[3][2] = fmaf(qa.w, kv.z, acc[3][2]);
        acc[3][3] = fmaf(qa.w, kv.w, acc[3][3]);
    }
    float* cb = g_qk + ((size_t)h * N) * N;
#pragma unroll
    for (int r = 0; r < 4; r++) {
        int i = i0 + ty * 4 + r;
        ((float4*)&cb[(size_t)i * N + j0])[tx] =
            make_float4(acc[r][0], acc[r][1], acc[r][2], acc[r][3]);
    }
}

// ---------------------------------------------------------------------------
// k_ab: A2/B3 (coalesced over i) + W4. grid 41, block 512.
// ---------------------------------------------------------------------------
__global__ __launch_bounds__(512) void k_ab(const float* __restrict__ w_ind) {
    const int b = blockIdx.x;
    const int t = threadIdx.x;
    if (b == 40) {                       // W4
        if (t < HEADS * 25) {
            int h = t / 25, c = (t % 25) / 5, cp = t % 5;
            float acc = 0.f;
#pragma unroll
            for (int d = 0; d < DH; d++)
                acc = fmaf(w_ind[(h * DH + d) * IND + c],
                           w_ind[(HID + h * DH + d) * IND + cp], acc);
            g_W4[t] = acc;
        }
        return;
    }
    const bool isA = b < 20;
    const int u = isA ? b : b - 20;
    const int h = u / 5, c = u % 5;
    __shared__ float ws[DH];
    if (t < DH)
        ws[t] = isA ? w_ind[(HID + h * DH + t) * IND + c]    // A2 pairs q with wk_ind
                    : w_ind[(h * DH + t) * IND + c];          // B3 pairs k with wq_ind
    __syncthreads();
    const float* src = g_qkv + (isA ? (h * DH) * N : (HID + h * DH) * N);
    float acc = 0.f;
#pragma unroll
    for (int d = 0; d < DH; d++)
        acc = fmaf(src[d * N + t], ws[d], acc);
    (isA ? g_A2 : g_B3)[(h * IND + c) * N + t] = acc;
}

// ---------------------------------------------------------------------------
// k_attn: fused sim -> softmax -> attn@v.  One block per (i, h), 512 threads.
// ---------------------------------------------------------------------------
__global__ __launch_bounds__(512) void k_attn(const float* __restrict__ indicator) {
    const int i = blockIdx.x;
    const int h = blockIdx.y;
    const int j = threadIdx.x;
    const int warp = j >> 5, lane = j & 31;

    __shared__ float a2s[IND];
    __shared__ float w4s[IND * IND];
    __shared__ __align__(16) float attn[N];
    __shared__ float red[16];

    if (j < IND)                a2s[j] = g_A2[(h * IND + j) * N + i];
    else if (j < IND + 25)      w4s[j - IND] = g_W4[h * 25 + (j - IND)];
    __syncthreads();

    // --- sim[j] ---
    float qk = g_qk[((size_t)h * N + i) * N + j];

    float iv[IND];
#pragma unroll
    for (int c = 0; c < IND; c++)
        iv[c] = indicator[(size_t)c * N * N + (size_t)i * N + j];

    float lin = 0.f;
#pragma unroll
    for (int c = 0; c < IND; c++)
        lin = fmaf(iv[c], a2s[c] + g_B3[(h * IND + c) * N + j], lin);

    float quad = 0.f;
#pragma unroll
    for (int c = 0; c < IND; c++) {
        float t2 = 0.f;
#pragma unroll
        for (int cp = 0; cp < IND; cp++)
            t2 = fmaf(w4s[c * IND + cp], iv[cp], t2);
        quad = fmaf(iv[c], t2, quad);
    }

    float sim = ATTN_SCALE * (qk + lin + quad);

    // --- softmax (unnormalized; scale at the end) ---
    float m = sim;
#pragma unroll
    for (int off = 16; off; off >>= 1)
        m = fmaxf(m, __shfl_xor_sync(0xffffffffu, m, off));
    if (lane == 0) red[warp] = m;
    __syncthreads();
    float gmax = red[0];
#pragma unroll
    for (int w = 1; w < 16; w++) gmax = fmaxf(gmax, red[w]);

    float e = __expf(sim - gmax);
    attn[j] = e;
    float s = e;
#pragma unroll
    for (int off = 16; off; off >>= 1)
        s += __shfl_xor_sync(0xffffffffu, s, off);
    __syncthreads();
    if (lane == 0) red[warp] = s;
    __syncthreads();
    float gsum = 0.f;
#pragma unroll
    for (int w = 0; w < 16; w++) gsum += red[w];
    const float inv = 1.0f / gsum;

    // --- out[h,d,i] = inv * sum_j attn[j] * v[h,d,j], float4-vectorized ---
    const float* vbase = g_qkv + (2 * HID + h * DH) * N;
    const float4* a4 = (const float4*)attn;
#pragma unroll
    for (int d = warp; d < DH; d += 16) {
        const float4* v4 = (const float4*)(vbase + d * N);
        float acc = 0.f;
#pragma unroll
        for (int q4 = lane; q4 < N / 4; q4 += 32) {
            float4 vv = v4[q4];
            float4 aa = a4[q4];
            acc = fmaf(aa.x, vv.x, acc);
            acc = fmaf(aa.y, vv.y, acc);
            acc = fmaf(aa.z, vv.z, acc);
            acc = fmaf(aa.w, vv.w, acc);
        }
#pragma unroll
        for (int off = 16; off; off >>= 1)
            acc += __shfl_xor_sync(0xffffffffu, acc, off);
        if (lane == 0) g_av[(h * DH + d) * N + i] = acc * inv;
    }
}

// ---------------------------------------------------------------------------
extern "C" void kernel_launch(void* const* d_in, const int* in_sizes, int n_in,
                              void* d_out, int out_size) {
    const float* x         = (const float*)d_in[0];   // (1,128,512)
    const float* indicator = (const float*)d_in[1];   // (1,5,512,512)
    const float* w_qkv     = (const float*)d_in[2];   // (384,128)
    const float* w_ind     = (const float*)d_in[3];   // (256,5)
    const float* w_out     = (const float*)d_in[4];   // (128,128)
    const float* b_out     = (const float*)d_in[5];   // (128,)
    float* out             = (float*)d_out;           // (1,128,512)

    float* qkv;  cudaGetSymbolAddress((void**)&qkv, g_qkv);
    float* av;   cudaGetSymbolAddress((void**)&av, g_av);

    // K1: qkv = w_qkv @ x         grid (512/64, 384/32)
    k_gemm<384, 128, 512, false><<<dim3(8, 12), 256>>>(w_qkv, x, nullptr, qkv);
    // K2: A2/B3/W4
    k_ab<<<41, 512>>>(w_ind);
    // K3: qk = q^T k per head
    k_qk<<<dim3(8, 8, 4), 256>>>();
    // K4: attention
    k_attn<<<dim3(512, 4), 512>>>(indicator);
    // K5: out = w_out @ av + b    grid (512/64, 128/32)
    k_gemm<128, 128, 512, true><<<dim3(8, 4), 256>>>(w_out, av, b_out, out);
}